// round 2
// baseline (speedup 1.0000x reference)
#include <cuda_runtime.h>

#define DIM      1024
#define NSTAGES  10
#define HALF_DIM (DIM / 2)            // 512
#define NTRIG    (NSTAGES * HALF_DIM) // 5120

// One warp processes one full row (1024 floats) register-resident.
// Element->thread mapping: p = c*128 + lane*4 + j   (c=0..7, j=0..3)
//   bits [1:0] = j  (stages 0-1: inside float4)
//   bits [6:2] = lane (stages 2-6: shfl_xor masks 1,2,4,8,16)
//   bits [9:7] = c  (stages 7-9: across registers)
__global__ __launch_bounds__(256) void butterfly_kernel(
    const float* __restrict__ x,
    const float* __restrict__ angles,
    float* __restrict__ out,
    int n_rows, int total_warps)
{
    __shared__ float2 s_trig[NTRIG];   // {cos, sin} per (stage, theta-index) : 40 KB

    const int tid = threadIdx.x;

    // Build trig table once per CTA (row-invariant).
    for (int i = tid; i < NTRIG; i += 256) {
        float sv, cv;
        sincosf(angles[i], &sv, &cv);
        s_trig[i] = make_float2(cv, sv);
    }
    __syncthreads();

    const int lane  = tid & 31;
    const int pbase = lane * 4;
    int gw = blockIdx.x * 8 + (tid >> 5);

    for (int row = gw; row < n_rows; row += total_warps) {
        float v[32];

        const float4* __restrict__ xr = (const float4*)(x + (size_t)row * DIM);
        #pragma unroll
        for (int c = 0; c < 8; c++) {
            float4 t = xr[c * 32 + lane];
            v[c*4+0] = t.x; v[c*4+1] = t.y; v[c*4+2] = t.z; v[c*4+3] = t.w;
        }

        // ---- stage 0: half=1, pairs (j, j+1) inside float4 ----
        #pragma unroll
        for (int c = 0; c < 8; c++) {
            #pragma unroll
            for (int j = 0; j < 4; j += 2) {
                int p = c*128 + pbase + j;               // left element (bit0 = 0)
                float2 cs = s_trig[0*HALF_DIM + (p >> 1)];
                float L = v[c*4+j], R = v[c*4+j+1];
                v[c*4+j]   = fmaf(cs.x, L,  cs.y * R);
                v[c*4+j+1] = fmaf(cs.x, R, -cs.y * L);
            }
        }

        // ---- stage 1: half=2, pairs (j, j+2) inside float4 ----
        #pragma unroll
        for (int c = 0; c < 8; c++) {
            #pragma unroll
            for (int j = 0; j < 2; j++) {
                int p  = c*128 + pbase + j;              // left element (bit1 = 0)
                int ti = ((p >> 2) << 1) | (p & 1);
                float2 cs = s_trig[1*HALF_DIM + ti];
                float L = v[c*4+j], R = v[c*4+j+2];
                v[c*4+j]   = fmaf(cs.x, L,  cs.y * R);
                v[c*4+j+2] = fmaf(cs.x, R, -cs.y * L);
            }
        }

        // ---- stages 2..6: half=4..64, partner lane = lane ^ (1<<(s-2)) ----
        #pragma unroll
        for (int s = 2; s <= 6; s++) {
            const int half = 1 << s;
            const int m    = 1 << (s - 2);
            const unsigned sgnmask = (unsigned)((lane >> (s - 2)) & 1) << 31;
            #pragma unroll
            for (int i = 0; i < 32; i++) {
                const int c = i >> 2, j = i & 3;
                int p  = c*128 + pbase + j;
                // theta index skips bit s of p -> identical for both lanes of a pair
                int ti = ((p >> (s + 1)) << s) | (p & (half - 1));
                float2 cs = s_trig[s*HALF_DIM + ti];
                float other = __shfl_xor_sync(0xffffffffu, v[i], m);
                // left lane: +sin, right lane: -sin (sign-bit XOR, ALU pipe)
                float ssin = __uint_as_float(__float_as_uint(cs.y) ^ sgnmask);
                v[i] = fmaf(cs.x, v[i], ssin * other);
            }
        }

        // ---- stages 7..9: half=128..512, partner register c ^ (1<<(s-7)) ----
        #pragma unroll
        for (int s = 7; s <= 9; s++) {
            const int half = 1 << s;
            const int cm   = 1 << (s - 7);
            #pragma unroll
            for (int c = 0; c < 8; c++) {
                if (c & cm) continue;                    // compile-time pruned
                #pragma unroll
                for (int j = 0; j < 4; j++) {
                    int p  = c*128 + pbase + j;          // left element (bit s = 0)
                    int ti = ((p >> (s + 1)) << s) | (p & (half - 1));
                    float2 cs = s_trig[s*HALF_DIM + ti];
                    const int iL = c*4 + j, iR = (c | cm)*4 + j;
                    float L = v[iL], R = v[iR];
                    v[iL] = fmaf(cs.x, L,  cs.y * R);
                    v[iR] = fmaf(cs.x, R, -cs.y * L);
                }
            }
        }

        float4* __restrict__ orow = (float4*)(out + (size_t)row * DIM);
        #pragma unroll
        for (int c = 0; c < 8; c++) {
            orow[c*32 + lane] = make_float4(v[c*4+0], v[c*4+1], v[c*4+2], v[c*4+3]);
        }
    }
}

extern "C" void kernel_launch(void* const* d_in, const int* in_sizes, int n_in,
                              void* d_out, int out_size)
{
    const float* x      = (const float*)d_in[0];
    const float* angles = (const float*)d_in[1];
    float*       out    = (float*)d_out;

    const int n_rows = in_sizes[0] / DIM;   // 16384
    const int blocks = 512;                 // 8 warps/CTA -> 4096 warps, 4 rows/warp
    const int total_warps = blocks * 8;

    butterfly_kernel<<<blocks, 256>>>(x, angles, out, n_rows, total_warps);
}

// round 3
// speedup vs baseline: 1.4531x; 1.4531x over previous
#include <cuda_runtime.h>

#define DIM      1024
#define NSTAGES  10
#define HALF_DIM 512
#define NTRIG    (NSTAGES * HALF_DIM)     // 5120 float2 = 40 KB

#define ROWS_PER_CTA 4                    // 256 threads = 8 warps = 4 rows x 2 warps
#define SMEM_BYTES   (NTRIG * 8 + ROWS_PER_CTA * DIM * 4)   // 40KB + 16KB = 57344

// Precomputed {cos, sin} table, built once per launch by a tiny kernel.
__device__ float2 g_trig[NTRIG];

__global__ void build_trig_kernel(const float* __restrict__ angles)
{
    int i = blockIdx.x * 256 + threadIdx.x;
    if (i < NTRIG) {
        float sv, cv;
        sincosf(angles[i], &sv, &cv);
        g_trig[i] = make_float2(cv, sv);
    }
}

// Two warps per row. Element mapping: p = w*512 + c*128 + lane*4 + j
//   bits [1:0]=j (stages 0-1), [6:2]=lane (stages 2-6 via shfl),
//   bits [8:7]=c (stages 7-8), bit 9=w (stage 9 via smem exchange).
__global__ __launch_bounds__(256, 4) void butterfly_kernel(
    const float* __restrict__ x,
    float* __restrict__ out,
    int n_quads)                          // n_rows / 4
{
    extern __shared__ float smem_raw[];
    float2* s_trig = (float2*)smem_raw;               // 5120 float2
    float4* s_xch4 = (float4*)(smem_raw + 2 * NTRIG); // 1024 float4 (4 rows)

    const int tid  = threadIdx.x;
    const int lane = tid & 31;
    const int ww   = tid >> 5;     // warp in CTA (0..7)
    const int w    = ww & 1;       // half-row selector (bit 9 of p)
    const int rw   = ww >> 1;      // row within CTA (0..3)

    // Copy trig table to shared (float4 = 2 entries per load).
    {
        const float4* gt = (const float4*)g_trig;
        float4*       st = (float4*)s_trig;
        #pragma unroll
        for (int i = 0; i < NTRIG / 2 / 256; i++)
            st[i * 256 + tid] = gt[i * 256 + tid];
    }
    __syncthreads();

    for (int quad = blockIdx.x; quad < n_quads; quad += gridDim.x) {
        const int row = quad * 4 + rw;
        float v[16];

        const float4* __restrict__ xr =
            (const float4*)(x + (size_t)row * DIM + w * 512);
        #pragma unroll
        for (int c = 0; c < 4; c++) {
            float4 t = __ldcs(xr + c * 32 + lane);
            v[c*4+0] = t.x; v[c*4+1] = t.y; v[c*4+2] = t.z; v[c*4+3] = t.w;
        }

        const int pbase = w * 512 + lane * 4;   // p for c=0, j=0

        // ---- stage 0: pairs (j0,j1),(j2,j3); ti = p>>1, 2 consecutive float2 ----
        #pragma unroll
        for (int c = 0; c < 4; c++) {
            int ti0 = (pbase + c * 128) >> 1;   // even
            float4 q = *(const float4*)&s_trig[ti0];
            float L0 = v[c*4+0], R0 = v[c*4+1];
            v[c*4+0] = fmaf(q.x, L0,  q.y * R0);
            v[c*4+1] = fmaf(q.x, R0, -q.y * L0);
            float L1 = v[c*4+2], R1 = v[c*4+3];
            v[c*4+2] = fmaf(q.z, L1,  q.w * R1);
            v[c*4+3] = fmaf(q.z, R1, -q.w * L1);
        }

        // ---- stage 1: pairs (j0,j2),(j1,j3); ti = ((p>>2)<<1)|(p&1) ----
        #pragma unroll
        for (int c = 0; c < 4; c++) {
            int ti0 = ((pbase + c * 128) >> 2) << 1;  // even
            float4 q = *(const float4*)&s_trig[HALF_DIM + ti0];
            float L0 = v[c*4+0], R0 = v[c*4+2];
            v[c*4+0] = fmaf(q.x, L0,  q.y * R0);
            v[c*4+2] = fmaf(q.x, R0, -q.y * L0);
            float L1 = v[c*4+1], R1 = v[c*4+3];
            v[c*4+1] = fmaf(q.z, L1,  q.w * R1);
            v[c*4+3] = fmaf(q.z, R1, -q.w * L1);
        }

        // ---- stages 2..6: partner lane = lane ^ (1<<(s-2)) ----
        #pragma unroll
        for (int s = 2; s <= 6; s++) {
            const int half = 1 << s;
            const int m    = 1 << (s - 2);
            const unsigned sgn = (unsigned)((lane >> (s - 2)) & 1) << 31;
            #pragma unroll
            for (int c = 0; c < 4; c++) {
                int p0  = pbase + c * 128;
                int ti0 = ((p0 >> (s + 1)) << s) | (p0 & (half - 1)); // mult of 4
                float4 q01 = *(const float4*)&s_trig[s * HALF_DIM + ti0];
                float4 q23 = *(const float4*)&s_trig[s * HALF_DIM + ti0 + 2];
                float cs[4] = {q01.x, q01.z, q23.x, q23.z};
                float sn[4] = {q01.y, q01.w, q23.y, q23.w};
                #pragma unroll
                for (int j = 0; j < 4; j++) {
                    float other = __shfl_xor_sync(0xffffffffu, v[c*4+j], m);
                    float ssin  = __uint_as_float(__float_as_uint(sn[j]) ^ sgn);
                    v[c*4+j] = fmaf(cs[j], v[c*4+j], ssin * other);
                }
            }
        }

        // ---- stage 7: pairs (c0,c1),(c2,c3) within thread ----
        #pragma unroll
        for (int cp = 0; cp < 2; cp++) {
            const int cl = cp * 2;
            int ti0 = (w * 2 + cp) * 128 + lane * 4;
            float4 q01 = *(const float4*)&s_trig[7 * HALF_DIM + ti0];
            float4 q23 = *(const float4*)&s_trig[7 * HALF_DIM + ti0 + 2];
            float cs[4] = {q01.x, q01.z, q23.x, q23.z};
            float sn[4] = {q01.y, q01.w, q23.y, q23.w};
            #pragma unroll
            for (int j = 0; j < 4; j++) {
                const int iL = cl * 4 + j, iR = (cl + 1) * 4 + j;
                float L = v[iL], R = v[iR];
                v[iL] = fmaf(cs[j], L,  sn[j] * R);
                v[iR] = fmaf(cs[j], R, -sn[j] * L);
            }
        }

        // ---- stage 8: pairs (c0,c2),(c1,c3) within thread ----
        #pragma unroll
        for (int cl = 0; cl < 2; cl++) {
            int ti0 = w * 256 + cl * 128 + lane * 4;
            float4 q01 = *(const float4*)&s_trig[8 * HALF_DIM + ti0];
            float4 q23 = *(const float4*)&s_trig[8 * HALF_DIM + ti0 + 2];
            float cs[4] = {q01.x, q01.z, q23.x, q23.z};
            float sn[4] = {q01.y, q01.w, q23.y, q23.w};
            #pragma unroll
            for (int j = 0; j < 4; j++) {
                const int iL = cl * 4 + j, iR = (cl + 2) * 4 + j;
                float L = v[iL], R = v[iR];
                v[iL] = fmaf(cs[j], L,  sn[j] * R);
                v[iR] = fmaf(cs[j], R, -sn[j] * L);
            }
        }

        // ---- stage 9: partner warp (p ^ 512) via smem exchange ----
        #pragma unroll
        for (int c = 0; c < 4; c++)
            s_xch4[rw * 256 + w * 128 + c * 32 + lane] =
                make_float4(v[c*4+0], v[c*4+1], v[c*4+2], v[c*4+3]);
        __syncthreads();
        {
            const unsigned sgn = (unsigned)w << 31;
            #pragma unroll
            for (int c = 0; c < 4; c++) {
                float4 o = s_xch4[rw * 256 + (w ^ 1) * 128 + c * 32 + lane];
                int ti0 = c * 128 + lane * 4;           // p & 511 (same both warps)
                float4 q01 = *(const float4*)&s_trig[9 * HALF_DIM + ti0];
                float4 q23 = *(const float4*)&s_trig[9 * HALF_DIM + ti0 + 2];
                float cs[4] = {q01.x, q01.z, q23.x, q23.z};
                float sn[4] = {q01.y, q01.w, q23.y, q23.w};
                float ot[4] = {o.x, o.y, o.z, o.w};
                #pragma unroll
                for (int j = 0; j < 4; j++) {
                    float ssin = __uint_as_float(__float_as_uint(sn[j]) ^ sgn);
                    v[c*4+j] = fmaf(cs[j], v[c*4+j], ssin * ot[j]);
                }
            }
        }
        __syncthreads();   // protect buffer before next iteration overwrites

        float4* __restrict__ orow = (float4*)(out + (size_t)row * DIM + w * 512);
        #pragma unroll
        for (int c = 0; c < 4; c++)
            __stcs(orow + c * 32 + lane,
                   make_float4(v[c*4+0], v[c*4+1], v[c*4+2], v[c*4+3]));
    }
}

extern "C" void kernel_launch(void* const* d_in, const int* in_sizes, int n_in,
                              void* d_out, int out_size)
{
    const float* x      = (const float*)d_in[0];
    const float* angles = (const float*)d_in[1];
    float*       out    = (float*)d_out;

    const int n_rows  = in_sizes[0] / DIM;     // 16384
    const int n_quads = n_rows / 4;            // 4096

    build_trig_kernel<<<(NTRIG + 255) / 256, 256>>>(angles);

    cudaFuncSetAttribute(butterfly_kernel,
                         cudaFuncAttributeMaxDynamicSharedMemorySize, SMEM_BYTES);

    butterfly_kernel<<<2048, 256, SMEM_BYTES>>>(x, out, n_quads);
}

// round 4
// speedup vs baseline: 1.8397x; 1.2660x over previous
#include <cuda_runtime.h>

#define DIM      1024
#define NSTAGES  10
#define HALF_DIM 512
#define NTRIG    (NSTAGES * HALF_DIM)     // 5120 float2 = 40 KB

// 8 warps = 4 warp-pairs; each warp-pair handles TWO rows (A and B) with the
// same element mapping, so every trig load is reused for both rows.
#define SMEM_BYTES (NTRIG * 8 + 4 * DIM * 4)   // 40KB trig + 16KB exchange = 57344

__device__ float2 g_trig[NTRIG];

__global__ void build_trig_kernel(const float* __restrict__ angles)
{
    int i = blockIdx.x * 256 + threadIdx.x;
    if (i < NTRIG) {
        float sv, cv;
        sincosf(angles[i], &sv, &cv);
        g_trig[i] = make_float2(cv, sv);
    }
}

__device__ __forceinline__ void rot(float& L, float& R, float c, float s)
{
    float l = L;
    L = fmaf(c, l,  s * R);
    R = fmaf(c, R, -s * l);
}

// Element mapping (per warp of a pair): p = w*512 + c*128 + lane*4 + j
//   bits [1:0]=j (stages 0-1), [6:2]=lane (stages 2-6 via shfl),
//   bits [8:7]=c (stages 7-8), bit 9=w (stage 9 via smem exchange).
__global__ __launch_bounds__(256, 4) void butterfly_kernel(
    const float* __restrict__ x,
    float* __restrict__ out)
{
    extern __shared__ float smem_raw[];
    float2* s_trig = (float2*)smem_raw;               // 5120 float2
    float4* s_xch4 = (float4*)(smem_raw + 2 * NTRIG); // 1024 float4 (4 rows)

    const int tid  = threadIdx.x;
    const int lane = tid & 31;
    const int ww   = tid >> 5;
    const int w    = ww & 1;       // half-row selector (bit 9)
    const int pr   = ww >> 1;      // warp-pair id (0..3)

    // Load precomputed trig table into shared (float4 = 2 entries per load).
    {
        const float4* gt = (const float4*)g_trig;
        float4*       st = (float4*)s_trig;
        #pragma unroll
        for (int i = 0; i < NTRIG / 2 / 256; i++)
            st[i * 256 + tid] = gt[i * 256 + tid];
    }
    __syncthreads();

    const int rowA = blockIdx.x * 8 + pr;       // rows [blk*8 .. blk*8+3]
    const int rowB = rowA + 4;                  // rows [blk*8+4 .. blk*8+7]

    float vA[16], vB[16];

    const float4* __restrict__ xrA = (const float4*)(x + (size_t)rowA * DIM + w * 512);
    const float4* __restrict__ xrB = (const float4*)(x + (size_t)rowB * DIM + w * 512);
    #pragma unroll
    for (int c = 0; c < 4; c++) {
        float4 a = xrA[c * 32 + lane];
        vA[c*4+0] = a.x; vA[c*4+1] = a.y; vA[c*4+2] = a.z; vA[c*4+3] = a.w;
        float4 b = xrB[c * 32 + lane];
        vB[c*4+0] = b.x; vB[c*4+1] = b.y; vB[c*4+2] = b.z; vB[c*4+3] = b.w;
    }

    const int pbase = w * 512 + lane * 4;   // p for c=0, j=0

    // ---- stage 0: pairs (j0,j1),(j2,j3); ti = p>>1 ----
    #pragma unroll
    for (int c = 0; c < 4; c++) {
        int ti0 = (pbase + c * 128) >> 1;   // even
        float4 q = *(const float4*)&s_trig[ti0];
        rot(vA[c*4+0], vA[c*4+1], q.x, q.y);
        rot(vB[c*4+0], vB[c*4+1], q.x, q.y);
        rot(vA[c*4+2], vA[c*4+3], q.z, q.w);
        rot(vB[c*4+2], vB[c*4+3], q.z, q.w);
    }

    // ---- stage 1: pairs (j0,j2),(j1,j3); ti = ((p>>2)<<1)|(p&1) ----
    #pragma unroll
    for (int c = 0; c < 4; c++) {
        int ti0 = ((pbase + c * 128) >> 2) << 1;  // even
        float4 q = *(const float4*)&s_trig[HALF_DIM + ti0];
        rot(vA[c*4+0], vA[c*4+2], q.x, q.y);
        rot(vB[c*4+0], vB[c*4+2], q.x, q.y);
        rot(vA[c*4+1], vA[c*4+3], q.z, q.w);
        rot(vB[c*4+1], vB[c*4+3], q.z, q.w);
    }

    // ---- stages 2..6: partner lane = lane ^ (1<<(s-2)) ----
    #pragma unroll
    for (int s = 2; s <= 6; s++) {
        const int half = 1 << s;
        const int m    = 1 << (s - 2);
        const unsigned sgn = (unsigned)((lane >> (s - 2)) & 1) << 31;
        #pragma unroll
        for (int c = 0; c < 4; c++) {
            int p0  = pbase + c * 128;
            int ti0 = ((p0 >> (s + 1)) << s) | (p0 & (half - 1)); // multiple of 4
            float4 q01 = *(const float4*)&s_trig[s * HALF_DIM + ti0];
            float4 q23 = *(const float4*)&s_trig[s * HALF_DIM + ti0 + 2];
            float cs[4] = {q01.x, q01.z, q23.x, q23.z};
            float sn[4] = {q01.y, q01.w, q23.y, q23.w};
            #pragma unroll
            for (int j = 0; j < 4; j++) {
                const int i = c*4 + j;
                float ssin = __uint_as_float(__float_as_uint(sn[j]) ^ sgn);
                float oA = __shfl_xor_sync(0xffffffffu, vA[i], m);
                vA[i] = fmaf(cs[j], vA[i], ssin * oA);
                float oB = __shfl_xor_sync(0xffffffffu, vB[i], m);
                vB[i] = fmaf(cs[j], vB[i], ssin * oB);
            }
        }
    }

    // ---- stage 7: pairs (c0,c1),(c2,c3) within thread ----
    #pragma unroll
    for (int cp = 0; cp < 2; cp++) {
        const int cl = cp * 2;
        int ti0 = (w * 2 + cp) * 128 + lane * 4;
        float4 q01 = *(const float4*)&s_trig[7 * HALF_DIM + ti0];
        float4 q23 = *(const float4*)&s_trig[7 * HALF_DIM + ti0 + 2];
        float cs[4] = {q01.x, q01.z, q23.x, q23.z};
        float sn[4] = {q01.y, q01.w, q23.y, q23.w};
        #pragma unroll
        for (int j = 0; j < 4; j++) {
            rot(vA[cl*4+j], vA[(cl+1)*4+j], cs[j], sn[j]);
            rot(vB[cl*4+j], vB[(cl+1)*4+j], cs[j], sn[j]);
        }
    }

    // ---- stage 8: pairs (c0,c2),(c1,c3) within thread ----
    #pragma unroll
    for (int cl = 0; cl < 2; cl++) {
        int ti0 = w * 256 + cl * 128 + lane * 4;
        float4 q01 = *(const float4*)&s_trig[8 * HALF_DIM + ti0];
        float4 q23 = *(const float4*)&s_trig[8 * HALF_DIM + ti0 + 2];
        float cs[4] = {q01.x, q01.z, q23.x, q23.z};
        float sn[4] = {q01.y, q01.w, q23.y, q23.w};
        #pragma unroll
        for (int j = 0; j < 4; j++) {
            rot(vA[cl*4+j], vA[(cl+2)*4+j], cs[j], sn[j]);
            rot(vB[cl*4+j], vB[(cl+2)*4+j], cs[j], sn[j]);
        }
    }

    // ---- stage 9: partner warp (p ^ 512) via smem exchange, row A then B ----
    const unsigned sgnw = (unsigned)w << 31;

    #pragma unroll
    for (int c = 0; c < 4; c++)
        s_xch4[pr * 256 + w * 128 + c * 32 + lane] =
            make_float4(vA[c*4+0], vA[c*4+1], vA[c*4+2], vA[c*4+3]);
    __syncthreads();
    #pragma unroll
    for (int c = 0; c < 4; c++) {
        float4 o = s_xch4[pr * 256 + (w ^ 1) * 128 + c * 32 + lane];
        int ti0 = c * 128 + lane * 4;           // p & 511 (same for both warps)
        float4 q01 = *(const float4*)&s_trig[9 * HALF_DIM + ti0];
        float4 q23 = *(const float4*)&s_trig[9 * HALF_DIM + ti0 + 2];
        float cs[4] = {q01.x, q01.z, q23.x, q23.z};
        float sn[4] = {q01.y, q01.w, q23.y, q23.w};
        float ot[4] = {o.x, o.y, o.z, o.w};
        #pragma unroll
        for (int j = 0; j < 4; j++) {
            float ssin = __uint_as_float(__float_as_uint(sn[j]) ^ sgnw);
            vA[c*4+j] = fmaf(cs[j], vA[c*4+j], ssin * ot[j]);
        }
    }
    __syncthreads();

    #pragma unroll
    for (int c = 0; c < 4; c++)
        s_xch4[pr * 256 + w * 128 + c * 32 + lane] =
            make_float4(vB[c*4+0], vB[c*4+1], vB[c*4+2], vB[c*4+3]);
    __syncthreads();
    #pragma unroll
    for (int c = 0; c < 4; c++) {
        float4 o = s_xch4[pr * 256 + (w ^ 1) * 128 + c * 32 + lane];
        int ti0 = c * 128 + lane * 4;
        float4 q01 = *(const float4*)&s_trig[9 * HALF_DIM + ti0];
        float4 q23 = *(const float4*)&s_trig[9 * HALF_DIM + ti0 + 2];
        float cs[4] = {q01.x, q01.z, q23.x, q23.z};
        float sn[4] = {q01.y, q01.w, q23.y, q23.w};
        float ot[4] = {o.x, o.y, o.z, o.w};
        #pragma unroll
        for (int j = 0; j < 4; j++) {
            float ssin = __uint_as_float(__float_as_uint(sn[j]) ^ sgnw);
            vB[c*4+j] = fmaf(cs[j], vB[c*4+j], ssin * ot[j]);
        }
    }

    float4* __restrict__ orA = (float4*)(out + (size_t)rowA * DIM + w * 512);
    float4* __restrict__ orB = (float4*)(out + (size_t)rowB * DIM + w * 512);
    #pragma unroll
    for (int c = 0; c < 4; c++) {
        orA[c*32 + lane] = make_float4(vA[c*4+0], vA[c*4+1], vA[c*4+2], vA[c*4+3]);
        orB[c*32 + lane] = make_float4(vB[c*4+0], vB[c*4+1], vB[c*4+2], vB[c*4+3]);
    }
}

extern "C" void kernel_launch(void* const* d_in, const int* in_sizes, int n_in,
                              void* d_out, int out_size)
{
    const float* x      = (const float*)d_in[0];
    const float* angles = (const float*)d_in[1];
    float*       out    = (float*)d_out;

    const int n_rows = in_sizes[0] / DIM;     // 16384
    const int blocks = n_rows / 8;            // 2048 (8 rows per CTA)

    build_trig_kernel<<<(NTRIG + 255) / 256, 256>>>(angles);

    cudaFuncSetAttribute(butterfly_kernel,
                         cudaFuncAttributeMaxDynamicSharedMemorySize, SMEM_BYTES);

    butterfly_kernel<<<blocks, 256, SMEM_BYTES>>>(x, out);
}